// round 1
// baseline (speedup 1.0000x reference)
#include <cuda_runtime.h>
#include <cuda_bf16.h>
#include <mma.h>

using namespace nvcuda;

// Problem constants
#define BATCH 8
#define SEQ   1024
#define DMODEL 1024
#define NHEAD 16
#define HDIM  64
#define KDIM  1024   // GEMM K for both projections

// Scratch (static device allocations are allowed)
__device__ float g_Q[BATCH * NHEAD * SEQ * HDIM];
__device__ float g_K[BATCH * NHEAD * SEQ * HDIM];
__device__ float g_V[BATCH * NHEAD * SEQ * HDIM];
__device__ float g_Vals[BATCH * SEQ * DMODEL];

// ---------------------------------------------------------------------------
// TF32 GEMM: C[M x NCOLS] = A[M x 1024] * B[1024 x NCOLS] + bias
// BM=128, BN=128, BK=16. 256 threads = 8 warps (4 along M x 2 along N),
// each warp: 32x64 via 2x4 fragments of 16x16.
// MODE 0: A = x, scatter into g_Q/g_K/g_V ([B,H,S,Hd])
// MODE 1: A = g_Vals, write C row-major to out
// ---------------------------------------------------------------------------
template<int NCOLS, int MODE>
__global__ __launch_bounds__(256)
void gemm_tf32(const float* __restrict__ Ain, const float* __restrict__ Bw,
               const float* __restrict__ bias, float* __restrict__ oC)
{
    __shared__ float As[128 * 16];
    __shared__ float Bs[16 * 128];
    __shared__ float Cs[8][16 * 20];

    const float* A = (MODE == 0) ? Ain : g_Vals;

    const int tid  = threadIdx.x;
    const int w    = tid >> 5;
    const int lane = tid & 31;
    const int wm   = w & 3;       // warp row (0..3) -> 32 rows
    const int wn   = w >> 2;      // warp col (0..1) -> 64 cols
    const int m0   = blockIdx.y * 128;
    const int n0   = blockIdx.x * 128;

    wmma::fragment<wmma::accumulator, 16, 16, 8, float> acc[2][4];
#pragma unroll
    for (int i = 0; i < 2; i++)
#pragma unroll
        for (int j = 0; j < 4; j++)
            wmma::fill_fragment(acc[i][j], 0.0f);

    const float4* A4 = reinterpret_cast<const float4*>(A);
    const float4* B4 = reinterpret_cast<const float4*>(Bw);
    float4* As4 = reinterpret_cast<float4*>(As);
    float4* Bs4 = reinterpret_cast<float4*>(Bs);

    for (int kt = 0; kt < KDIM / 16; ++kt) {
        const int k0 = kt * 16;
        __syncthreads();
        // A tile: 128x16 floats = 512 float4 (row r holds 4 float4)
        {
            int c = tid;
#pragma unroll
            for (int it = 0; it < 2; ++it, c += 256) {
                int r = c >> 2, q = c & 3;
                As4[c] = A4[(m0 + r) * (KDIM / 4) + (k0 >> 2) + q];
            }
            c = tid;
#pragma unroll
            for (int it = 0; it < 2; ++it, c += 256) {
                int r = c >> 5, q = c & 31;
                Bs4[c] = B4[(k0 + r) * (NCOLS / 4) + (n0 >> 2) + q];
            }
        }
        __syncthreads();
#pragma unroll
        for (int kk = 0; kk < 16; kk += 8) {
            wmma::fragment<wmma::matrix_a, 16, 16, 8, wmma::precision::tf32, wmma::row_major> af[2];
            wmma::fragment<wmma::matrix_b, 16, 16, 8, wmma::precision::tf32, wmma::row_major> bf[4];
#pragma unroll
            for (int i = 0; i < 2; i++) {
                wmma::load_matrix_sync(af[i], &As[(wm * 32 + i * 16) * 16 + kk], 16);
#pragma unroll
                for (int e = 0; e < af[i].num_elements; e++)
                    af[i].x[e] = wmma::__float_to_tf32(af[i].x[e]);
            }
#pragma unroll
            for (int j = 0; j < 4; j++) {
                wmma::load_matrix_sync(bf[j], &Bs[kk * 128 + wn * 64 + j * 16], 128);
#pragma unroll
                for (int e = 0; e < bf[j].num_elements; e++)
                    bf[j].x[e] = wmma::__float_to_tf32(bf[j].x[e]);
            }
#pragma unroll
            for (int i = 0; i < 2; i++)
#pragma unroll
                for (int j = 0; j < 4; j++)
                    wmma::mma_sync(acc[i][j], af[i], bf[j], acc[i][j]);
        }
    }
    __syncthreads();

    // Epilogue: per-warp staging tile, add bias, write/scatter
#pragma unroll
    for (int i = 0; i < 2; i++) {
#pragma unroll
        for (int j = 0; j < 4; j++) {
            wmma::store_matrix_sync(&Cs[w][0], acc[i][j], 20, wmma::mem_row_major);
            __syncwarp();
            const int mbase = m0 + wm * 32 + i * 16;
            const int ebase = n0 + wn * 64 + j * 16;
            for (int t = lane; t < 256; t += 32) {
                int rr = t >> 4, cc = t & 15;
                int m = mbase + rr;
                int e = ebase + cc;
                float v = Cs[w][rr * 20 + cc] + bias[e];
                if (MODE == 0) {
                    int b = m >> 10, s = m & 1023;
                    int h = e / 192;
                    int jj = e - h * 192;
                    int dd = jj & 63;
                    float* dst = (jj < 64) ? g_Q : (jj < 128) ? g_K : g_V;
                    dst[((b * NHEAD + h) * SEQ + s) * HDIM + dd] = v;
                } else {
                    oC[m * NCOLS + e] = v;
                }
            }
            __syncwarp();
        }
    }
}

// ---------------------------------------------------------------------------
// Flash attention: 1 CTA per (b, h, 128-query tile). kv tiles of 64.
// Online softmax; QK^T and P*V via wmma tf32. Output to g_Vals [B,S,D].
// ---------------------------------------------------------------------------
__global__ __launch_bounds__(256)
void attn_kernel()
{
    extern __shared__ float sm[];
    float* Qs   = sm;             // 128*64
    float* Ks   = Qs + 8192;      // 64*64
    float* Vs   = Ks + 4096;      // 64*64
    float* Ss   = Vs + 4096;      // 128*64
    float* Os   = Ss + 8192;      // 128*64
    float* mrow = Os + 8192;      // 128
    float* lrow = mrow + 128;     // 128

    const int tid  = threadIdx.x;
    const int w    = tid >> 5;
    const int wm   = w & 3;   // 4 warps along 128 rows -> 32 rows each
    const int wn   = w >> 2;  // 2 warps along 64 cols  -> 32 cols each
    const int qt = blockIdx.x, h = blockIdx.y, b = blockIdx.z;

    const float* Qg = g_Q + ((b * NHEAD + h) * SEQ + qt * 128) * HDIM;
    const float* Kg = g_K + ((size_t)(b * NHEAD + h) * SEQ) * HDIM;
    const float* Vg = g_V + ((size_t)(b * NHEAD + h) * SEQ) * HDIM;

    const float4* Qg4 = reinterpret_cast<const float4*>(Qg);
    const float4* Kg4 = reinterpret_cast<const float4*>(Kg);
    const float4* Vg4 = reinterpret_cast<const float4*>(Vg);
    float4* Qs4 = reinterpret_cast<float4*>(Qs);
    float4* Ks4 = reinterpret_cast<float4*>(Ks);
    float4* Vs4 = reinterpret_cast<float4*>(Vs);
    float4* Os4 = reinterpret_cast<float4*>(Os);

    // Load Q (pre-scaled by 1/sqrt(Hd) = 0.125) and init O, m, l
    for (int c = tid; c < 2048; c += 256) {
        float4 v = Qg4[c];
        v.x *= 0.125f; v.y *= 0.125f; v.z *= 0.125f; v.w *= 0.125f;
        Qs4[c] = v;
        Os4[c] = make_float4(0.f, 0.f, 0.f, 0.f);
    }
    if (tid < 128) { mrow[tid] = -1e30f; lrow[tid] = 0.f; }

    for (int kt = 0; kt < SEQ / 64; ++kt) {
        __syncthreads();
        for (int c = tid; c < 1024; c += 256) {
            Ks4[c] = Kg4[kt * 1024 + c];
            Vs4[c] = Vg4[kt * 1024 + c];
        }
        __syncthreads();

        // S = Qs(128x64) * Ks^T(64x64): warp handles 32x32 via 2x2 frags
        {
            wmma::fragment<wmma::accumulator, 16, 16, 8, float> sacc[2][2];
#pragma unroll
            for (int i = 0; i < 2; i++)
#pragma unroll
                for (int j = 0; j < 2; j++)
                    wmma::fill_fragment(sacc[i][j], 0.0f);
#pragma unroll
            for (int d = 0; d < HDIM; d += 8) {
                wmma::fragment<wmma::matrix_a, 16, 16, 8, wmma::precision::tf32, wmma::row_major> af[2];
                wmma::fragment<wmma::matrix_b, 16, 16, 8, wmma::precision::tf32, wmma::col_major> bf[2];
#pragma unroll
                for (int i = 0; i < 2; i++) {
                    wmma::load_matrix_sync(af[i], &Qs[(wm * 32 + i * 16) * 64 + d], 64);
#pragma unroll
                    for (int e = 0; e < af[i].num_elements; e++)
                        af[i].x[e] = wmma::__float_to_tf32(af[i].x[e]);
                }
#pragma unroll
                for (int j = 0; j < 2; j++) {
                    wmma::load_matrix_sync(bf[j], &Ks[(wn * 32 + j * 16) * 64 + d], 64);
#pragma unroll
                    for (int e = 0; e < bf[j].num_elements; e++)
                        bf[j].x[e] = wmma::__float_to_tf32(bf[j].x[e]);
                }
#pragma unroll
                for (int i = 0; i < 2; i++)
#pragma unroll
                    for (int j = 0; j < 2; j++)
                        wmma::mma_sync(sacc[i][j], af[i], bf[j], sacc[i][j]);
            }
#pragma unroll
            for (int i = 0; i < 2; i++)
#pragma unroll
                for (int j = 0; j < 2; j++)
                    wmma::store_matrix_sync(&Ss[(wm * 32 + i * 16) * 64 + wn * 32 + j * 16],
                                            sacc[i][j], 64, wmma::mem_row_major);
        }
        __syncthreads();

        // Online softmax over this kv tile; rescale O rows by alpha
        if (tid < 128) {
            float* srow = Ss + tid * 64;
            float mo = mrow[tid];
            float mx = mo;
#pragma unroll 8
            for (int d = 0; d < 64; d++) mx = fmaxf(mx, srow[d]);
            float alpha = __expf(mo - mx);
            float sum = 0.f;
#pragma unroll 8
            for (int d = 0; d < 64; d++) {
                float p = __expf(srow[d] - mx);
                srow[d] = p;
                sum += p;
            }
            lrow[tid] = lrow[tid] * alpha + sum;
            mrow[tid] = mx;
            float* orow = Os + tid * 64;
#pragma unroll 8
            for (int d = 0; d < 64; d++) orow[d] *= alpha;
        }
        __syncthreads();

        // O += P(128x64) * V(64x64): accumulate into Os via load/mma/store
        {
#pragma unroll
            for (int i = 0; i < 2; i++) {
#pragma unroll
                for (int j = 0; j < 2; j++) {
                    wmma::fragment<wmma::accumulator, 16, 16, 8, float> oacc;
                    float* optr = &Os[(wm * 32 + i * 16) * 64 + wn * 32 + j * 16];
                    wmma::load_matrix_sync(oacc, optr, 64, wmma::mem_row_major);
#pragma unroll
                    for (int kk = 0; kk < 64; kk += 8) {
                        wmma::fragment<wmma::matrix_a, 16, 16, 8, wmma::precision::tf32, wmma::row_major> af;
                        wmma::fragment<wmma::matrix_b, 16, 16, 8, wmma::precision::tf32, wmma::row_major> bf;
                        wmma::load_matrix_sync(af, &Ss[(wm * 32 + i * 16) * 64 + kk], 64);
#pragma unroll
                        for (int e = 0; e < af.num_elements; e++)
                            af.x[e] = wmma::__float_to_tf32(af.x[e]);
                        wmma::load_matrix_sync(bf, &Vs[kk * 64 + wn * 32 + j * 16], 64);
#pragma unroll
                        for (int e = 0; e < bf.num_elements; e++)
                            bf.x[e] = wmma::__float_to_tf32(bf.x[e]);
                        wmma::mma_sync(oacc, af, bf, oacc);
                    }
                    wmma::store_matrix_sync(optr, oacc, 64, wmma::mem_row_major);
                }
            }
        }
        __syncthreads();
    }

    // Finalize: O /= l, write to g_Vals [B, S, D] at column h*64
    __syncthreads();
    for (int idx = tid; idx < 8192; idx += 256) {
        int r = idx >> 6, d = idx & 63;
        float v = Os[idx] / lrow[r];
        g_Vals[((size_t)(b * SEQ + qt * 128 + r)) * DMODEL + h * HDIM + d] = v;
    }
}

// ---------------------------------------------------------------------------
extern "C" void kernel_launch(void* const* d_in, const int* in_sizes, int n_in,
                              void* d_out, int out_size)
{
    const float* x    = (const float*)d_in[0];
    const float* Wqkv = (const float*)d_in[1];
    const float* bqkv = (const float*)d_in[2];
    const float* Wo   = (const float*)d_in[3];
    const float* bo   = (const float*)d_in[4];
    float* out = (float*)d_out;

    // 1) QKV projection + scatter into [B,H,S,Hd]
    gemm_tf32<3 * DMODEL, 0><<<dim3(24, 64), 256>>>(x, Wqkv, bqkv, nullptr);

    // 2) Attention (flash-style) -> g_Vals [B,S,D]
    const int smem_bytes = (8192 + 4096 + 4096 + 8192 + 8192 + 128 + 128) * (int)sizeof(float);
    cudaFuncSetAttribute(attn_kernel, cudaFuncAttributeMaxDynamicSharedMemorySize, smem_bytes);
    attn_kernel<<<dim3(SEQ / 128, NHEAD, BATCH), 256, smem_bytes>>>();

    // 3) Output projection -> d_out
    gemm_tf32<DMODEL, 1><<<dim3(8, 64), 256>>>(nullptr, Wo, bo, out);
}

// round 2
// speedup vs baseline: 2.4210x; 2.4210x over previous
#include <cuda_runtime.h>
#include <cuda_bf16.h>
#include <mma.h>
#include <cstdint>

using namespace nvcuda;

#define BATCH 8
#define SEQ   1024
#define DMODEL 1024
#define NHEAD 16
#define HDIM  64
#define KDIM  1024

__device__ float g_Q[BATCH * NHEAD * SEQ * HDIM];
__device__ float g_K[BATCH * NHEAD * SEQ * HDIM];
__device__ float g_V[BATCH * NHEAD * SEQ * HDIM];
__device__ float g_Vals[BATCH * SEQ * DMODEL];

// ---------------- helpers ----------------
__device__ __forceinline__ void cp_async16(void* smem_dst, const void* gsrc) {
    uint32_t s = (uint32_t)__cvta_generic_to_shared(smem_dst);
    asm volatile("cp.async.cg.shared.global [%0], [%1], 16;\n" :: "r"(s), "l"(gsrc));
}
__device__ __forceinline__ void cp_commit() { asm volatile("cp.async.commit_group;\n"); }
template<int N> __device__ __forceinline__ void cp_wait() {
    asm volatile("cp.async.wait_group %0;\n" :: "n"(N));
}
__device__ __forceinline__ uint32_t f2tf(float f) {
    uint32_t r; asm("cvt.rna.tf32.f32 %0, %1;" : "=r"(r) : "f"(f)); return r;
}
__device__ __forceinline__ void mma_tf32(float* d, const uint32_t* a, uint32_t b0, uint32_t b1) {
    asm volatile(
        "mma.sync.aligned.m16n8k8.row.col.f32.tf32.tf32.f32 "
        "{%0,%1,%2,%3}, {%4,%5,%6,%7}, {%8,%9}, {%0,%1,%2,%3};\n"
        : "+f"(d[0]), "+f"(d[1]), "+f"(d[2]), "+f"(d[3])
        : "r"(a[0]), "r"(a[1]), "r"(a[2]), "r"(a[3]), "r"(b0), "r"(b1));
}

// ---------------------------------------------------------------------------
// TF32 GEMM: C[M x NCOLS] = A[M x 1024] * B[1024 x NCOLS] + bias
// BM=128 BN=128 BK=32, cp.async double-buffered. 8 warps, warp tile 32x64.
// MODE 0: scatter into g_Q/g_K/g_V.  MODE 1: write row-major to oC.
// ---------------------------------------------------------------------------
#define GEMM_AS (128 * 36)
#define GEMM_BS (32 * 132)
#define GEMM_SMEM_FLOATS (2 * GEMM_AS + 2 * GEMM_BS + 8 * 320)

template<int NCOLS, int MODE>
__global__ __launch_bounds__(256)
void gemm_tf32(const float* __restrict__ Ain, const float* __restrict__ Bw,
               const float* __restrict__ bias, float* __restrict__ oC)
{
    extern __shared__ float sm[];
    float* As0 = sm;
    float* As1 = sm + GEMM_AS;
    float* Bs0 = sm + 2 * GEMM_AS;
    float* Bs1 = Bs0 + GEMM_BS;
    float* Cs  = Bs0 + 2 * GEMM_BS;

    const float* A = (MODE == 0) ? Ain : g_Vals;

    const int tid  = threadIdx.x;
    const int w    = tid >> 5;
    const int lane = tid & 31;
    const int wm   = w & 3;
    const int wn   = w >> 2;
    const int m0   = blockIdx.y * 128;
    const int n0   = blockIdx.x * 128;

    wmma::fragment<wmma::accumulator, 16, 16, 8, float> acc[2][4];
#pragma unroll
    for (int i = 0; i < 2; i++)
#pragma unroll
        for (int j = 0; j < 4; j++)
            wmma::fill_fragment(acc[i][j], 0.0f);

    auto load_stage = [&](int kt, float* Ad, float* Bd) {
        const float* Asrc = A + (size_t)m0 * KDIM + kt * 32;
#pragma unroll
        for (int it = 0; it < 4; ++it) {
            int c = tid + it * 256;            // 0..1023
            int r = c >> 3, q = c & 7;         // 128 rows x 8 float4
            cp_async16(&Ad[r * 36 + q * 4], Asrc + r * KDIM + q * 4);
        }
        const float* Bsrc = Bw + (size_t)(kt * 32) * NCOLS + n0;
#pragma unroll
        for (int it = 0; it < 4; ++it) {
            int c = tid + it * 256;
            int r = c >> 5, q = c & 31;        // 32 rows x 32 float4
            cp_async16(&Bd[r * 132 + q * 4], Bsrc + r * NCOLS + q * 4);
        }
    };

    load_stage(0, As0, Bs0);
    cp_commit();

    for (int kt = 0; kt < KDIM / 32; ++kt) {
        if (kt + 1 < KDIM / 32) {
            load_stage(kt + 1, (kt & 1) ? As0 : As1, (kt & 1) ? Bs0 : Bs1);
            cp_commit();
            cp_wait<1>();
        } else {
            cp_wait<0>();
        }
        __syncthreads();

        float* Ac = (kt & 1) ? As1 : As0;
        float* Bc = (kt & 1) ? Bs1 : Bs0;
#pragma unroll
        for (int kk = 0; kk < 32; kk += 8) {
            wmma::fragment<wmma::matrix_a, 16, 16, 8, wmma::precision::tf32, wmma::row_major> af[2];
            wmma::fragment<wmma::matrix_b, 16, 16, 8, wmma::precision::tf32, wmma::row_major> bf[4];
#pragma unroll
            for (int i = 0; i < 2; i++) {
                wmma::load_matrix_sync(af[i], &Ac[(wm * 32 + i * 16) * 36 + kk], 36);
#pragma unroll
                for (int e = 0; e < af[i].num_elements; e++)
                    af[i].x[e] = wmma::__float_to_tf32(af[i].x[e]);
            }
#pragma unroll
            for (int j = 0; j < 4; j++) {
                wmma::load_matrix_sync(bf[j], &Bc[kk * 132 + wn * 64 + j * 16], 132);
#pragma unroll
                for (int e = 0; e < bf[j].num_elements; e++)
                    bf[j].x[e] = wmma::__float_to_tf32(bf[j].x[e]);
            }
#pragma unroll
            for (int i = 0; i < 2; i++)
#pragma unroll
                for (int j = 0; j < 4; j++)
                    wmma::mma_sync(acc[i][j], af[i], bf[j], acc[i][j]);
        }
        __syncthreads();
    }

    // Epilogue
#pragma unroll
    for (int i = 0; i < 2; i++) {
#pragma unroll
        for (int j = 0; j < 4; j++) {
            wmma::store_matrix_sync(&Cs[w * 320], acc[i][j], 20, wmma::mem_row_major);
            __syncwarp();
            const int mbase = m0 + wm * 32 + i * 16;
            const int ebase = n0 + wn * 64 + j * 16;
            for (int t = lane; t < 256; t += 32) {
                int rr = t >> 4, cc = t & 15;
                int m = mbase + rr;
                int e = ebase + cc;
                float v = Cs[w * 320 + rr * 20 + cc] + bias[e];
                if (MODE == 0) {
                    int b = m >> 10, s = m & 1023;
                    int h = e / 192;
                    int jj = e - h * 192;
                    int dd = jj & 63;
                    float* dst = (jj < 64) ? g_Q : (jj < 128) ? g_K : g_V;
                    dst[((b * NHEAD + h) * SEQ + s) * HDIM + dd] = v;
                } else {
                    oC[m * NCOLS + e] = v;
                }
            }
            __syncwarp();
        }
    }
}

// ---------------------------------------------------------------------------
// FlashAttention-2 style: 1 CTA per (b, h, 128 q-rows). 8 warps x 16 q-rows.
// Q and O register-resident. Raw mma.sync m16n8k8 tf32. KV tile = 64,
// double-buffered cp.async. P goes through a per-warp padded smem buffer
// for the C-layout -> A-layout fixup.
// ---------------------------------------------------------------------------
#define KVS 68                       // padded row stride (floats)
#define ATTN_KV (64 * KVS)           // one K or V tile
#define ATTN_SMEM_FLOATS (4 * ATTN_KV + 8 * 16 * KVS)

__global__ __launch_bounds__(256, 1)
void attn_kernel()
{
    extern __shared__ float sm[];
    float* Kb0 = sm;
    float* Kb1 = Kb0 + ATTN_KV;
    float* Vb0 = Kb1 + ATTN_KV;
    float* Vb1 = Vb0 + ATTN_KV;
    float* Pall = Vb1 + ATTN_KV;

    const int tid  = threadIdx.x;
    const int w    = tid >> 5;
    const int lane = tid & 31;
    const int g    = lane >> 2;     // 0..7
    const int t4   = lane & 3;      // 0..3
    const int qt = blockIdx.x, h = blockIdx.y, b = blockIdx.z;

    const float* Qg = g_Q + ((size_t)((b * NHEAD + h) * SEQ) + qt * 128 + w * 16) * HDIM;
    const float* Kg = g_K + (size_t)((b * NHEAD + h) * SEQ) * HDIM;
    const float* Vg = g_V + (size_t)((b * NHEAD + h) * SEQ) * HDIM;
    float* Pw = Pall + w * 16 * KVS;

    auto load_kv = [&](int kt, float* Kd, float* Vd) {
        const float* Ks = Kg + (size_t)kt * 64 * HDIM;
        const float* Vs = Vg + (size_t)kt * 64 * HDIM;
#pragma unroll
        for (int it = 0; it < 4; ++it) {
            int c = tid + it * 256;          // 0..1023
            int r = c >> 4, q = c & 15;      // 64 rows x 16 float4
            cp_async16(&Kd[r * KVS + q * 4], Ks + r * HDIM + q * 4);
        }
#pragma unroll
        for (int it = 0; it < 4; ++it) {
            int c = tid + it * 256;
            int r = c >> 4, q = c & 15;
            cp_async16(&Vd[r * KVS + q * 4], Vs + r * HDIM + q * 4);
        }
    };

    // Q -> a-frags for all 8 k-steps, pre-scaled by 1/sqrt(64)
    uint32_t qa[8][4];
#pragma unroll
    for (int ks = 0; ks < 8; ++ks) {
        qa[ks][0] = f2tf(Qg[g * HDIM       + ks * 8 + t4    ] * 0.125f);
        qa[ks][1] = f2tf(Qg[(g + 8) * HDIM + ks * 8 + t4    ] * 0.125f);
        qa[ks][2] = f2tf(Qg[g * HDIM       + ks * 8 + t4 + 4] * 0.125f);
        qa[ks][3] = f2tf(Qg[(g + 8) * HDIM + ks * 8 + t4 + 4] * 0.125f);
    }

    float oacc[8][4];
#pragma unroll
    for (int j = 0; j < 8; j++)
#pragma unroll
        for (int c = 0; c < 4; c++) oacc[j][c] = 0.f;
    float m0r = -1e30f, m1r = -1e30f, l0 = 0.f, l1 = 0.f;

    load_kv(0, Kb0, Vb0);
    cp_commit();

    for (int kt = 0; kt < SEQ / 64; ++kt) {
        if (kt + 1 < SEQ / 64) {
            load_kv(kt + 1, (kt & 1) ? Kb0 : Kb1, (kt & 1) ? Vb0 : Vb1);
            cp_commit();
            cp_wait<1>();
        } else {
            cp_wait<0>();
        }
        __syncthreads();

        float* Kc = (kt & 1) ? Kb1 : Kb0;
        float* Vc = (kt & 1) ? Vb1 : Vb0;

        // ---- S = Q @ K^T  (16 x 64 per warp), registers ----
        float sacc[8][4];
#pragma unroll
        for (int j = 0; j < 8; j++)
#pragma unroll
            for (int c = 0; c < 4; c++) sacc[j][c] = 0.f;

#pragma unroll
        for (int j = 0; j < 8; ++j) {       // kv column block (s)
            const float* Kr = Kc + (j * 8 + g) * KVS;
#pragma unroll
            for (int ks = 0; ks < 8; ++ks) { // head-dim k-step
                uint32_t b0 = f2tf(Kr[ks * 8 + t4]);
                uint32_t b1 = f2tf(Kr[ks * 8 + t4 + 4]);
                mma_tf32(sacc[j], qa[ks], b0, b1);
            }
        }

        // ---- online softmax (registers + quad shuffles) ----
        float mx0 = m0r, mx1 = m1r;
#pragma unroll
        for (int j = 0; j < 8; j++) {
            mx0 = fmaxf(mx0, fmaxf(sacc[j][0], sacc[j][1]));
            mx1 = fmaxf(mx1, fmaxf(sacc[j][2], sacc[j][3]));
        }
        mx0 = fmaxf(mx0, __shfl_xor_sync(0xffffffffu, mx0, 1));
        mx0 = fmaxf(mx0, __shfl_xor_sync(0xffffffffu, mx0, 2));
        mx1 = fmaxf(mx1, __shfl_xor_sync(0xffffffffu, mx1, 1));
        mx1 = fmaxf(mx1, __shfl_xor_sync(0xffffffffu, mx1, 2));

        float a0 = __expf(m0r - mx0);
        float a1 = __expf(m1r - mx1);
        m0r = mx0; m1r = mx1;

        float s0 = 0.f, s1 = 0.f;
#pragma unroll
        for (int j = 0; j < 8; j++) {
            float p;
            p = __expf(sacc[j][0] - mx0); sacc[j][0] = p; s0 += p;
            p = __expf(sacc[j][1] - mx0); sacc[j][1] = p; s0 += p;
            p = __expf(sacc[j][2] - mx1); sacc[j][2] = p; s1 += p;
            p = __expf(sacc[j][3] - mx1); sacc[j][3] = p; s1 += p;
        }
        s0 += __shfl_xor_sync(0xffffffffu, s0, 1);
        s0 += __shfl_xor_sync(0xffffffffu, s0, 2);
        s1 += __shfl_xor_sync(0xffffffffu, s1, 1);
        s1 += __shfl_xor_sync(0xffffffffu, s1, 2);
        l0 = l0 * a0 + s0;
        l1 = l1 * a1 + s1;

#pragma unroll
        for (int j = 0; j < 8; j++) {
            oacc[j][0] *= a0; oacc[j][1] *= a0;
            oacc[j][2] *= a1; oacc[j][3] *= a1;
        }

        // ---- stage P (C layout) to smem, reload as A frags ----
#pragma unroll
        for (int j = 0; j < 8; j++) {
            Pw[g * KVS       + j * 8 + t4 * 2    ] = sacc[j][0];
            Pw[g * KVS       + j * 8 + t4 * 2 + 1] = sacc[j][1];
            Pw[(g + 8) * KVS + j * 8 + t4 * 2    ] = sacc[j][2];
            Pw[(g + 8) * KVS + j * 8 + t4 * 2 + 1] = sacc[j][3];
        }
        __syncwarp();

        uint32_t pa[8][4];
#pragma unroll
        for (int ks = 0; ks < 8; ++ks) {
            pa[ks][0] = f2tf(Pw[g * KVS       + ks * 8 + t4    ]);
            pa[ks][1] = f2tf(Pw[(g + 8) * KVS + ks * 8 + t4    ]);
            pa[ks][2] = f2tf(Pw[g * KVS       + ks * 8 + t4 + 4]);
            pa[ks][3] = f2tf(Pw[(g + 8) * KVS + ks * 8 + t4 + 4]);
        }

        // ---- O += P @ V ----
#pragma unroll
        for (int j = 0; j < 8; ++j) {        // output head-dim block
#pragma unroll
            for (int ks = 0; ks < 8; ++ks) { // kv k-step (s)
                uint32_t b0 = f2tf(Vc[(ks * 8 + t4    ) * KVS + j * 8 + g]);
                uint32_t b1 = f2tf(Vc[(ks * 8 + t4 + 4) * KVS + j * 8 + g]);
                mma_tf32(oacc[j], pa[ks], b0, b1);
            }
        }
        __syncthreads();
    }

    // ---- finalize: O /= l, write to g_Vals [B,S,D] ----
    float inv0 = 1.f / l0, inv1 = 1.f / l1;
    const int row0 = qt * 128 + w * 16 + g;
    float* out0 = g_Vals + (size_t)(b * SEQ + row0) * DMODEL + h * HDIM;
    float* out1 = out0 + 8 * DMODEL;
#pragma unroll
    for (int j = 0; j < 8; ++j) {
        *reinterpret_cast<float2*>(out0 + j * 8 + t4 * 2) =
            make_float2(oacc[j][0] * inv0, oacc[j][1] * inv0);
        *reinterpret_cast<float2*>(out1 + j * 8 + t4 * 2) =
            make_float2(oacc[j][2] * inv1, oacc[j][3] * inv1);
    }
}

// ---------------------------------------------------------------------------
extern "C" void kernel_launch(void* const* d_in, const int* in_sizes, int n_in,
                              void* d_out, int out_size)
{
    const float* x    = (const float*)d_in[0];
    const float* Wqkv = (const float*)d_in[1];
    const float* bqkv = (const float*)d_in[2];
    const float* Wo   = (const float*)d_in[3];
    const float* bo   = (const float*)d_in[4];
    float* out = (float*)d_out;

    const int gemm_smem = GEMM_SMEM_FLOATS * (int)sizeof(float);
    const int attn_smem = ATTN_SMEM_FLOATS * (int)sizeof(float);

    cudaFuncSetAttribute(gemm_tf32<3 * DMODEL, 0>,
                         cudaFuncAttributeMaxDynamicSharedMemorySize, gemm_smem);
    cudaFuncSetAttribute(gemm_tf32<DMODEL, 1>,
                         cudaFuncAttributeMaxDynamicSharedMemorySize, gemm_smem);
    cudaFuncSetAttribute(attn_kernel,
                         cudaFuncAttributeMaxDynamicSharedMemorySize, attn_smem);

    // 1) QKV projection + scatter into [B,H,S,Hd]
    gemm_tf32<3 * DMODEL, 0><<<dim3(24, 64), 256, gemm_smem>>>(x, Wqkv, bqkv, nullptr);

    // 2) Attention -> g_Vals [B,S,D]
    attn_kernel<<<dim3(SEQ / 128, NHEAD, BATCH), 256, attn_smem>>>();

    // 3) Output projection -> d_out
    gemm_tf32<DMODEL, 1><<<dim3(8, 64), 256, gemm_smem>>>(nullptr, Wo, bo, out);
}

// round 6
// speedup vs baseline: 2.7134x; 1.1208x over previous
#include <cuda_runtime.h>
#include <cuda_fp16.h>
#include <mma.h>
#include <cstdint>

using namespace nvcuda;

#define BATCH 8
#define SEQ   1024
#define DMODEL 1024
#define NHEAD 16
#define HDIM  64
#define KDIM  1024

// float scratch (round-2 verified path)
__device__ float g_Qf[BATCH * NHEAD * SEQ * HDIM];
__device__ float g_Kf[BATCH * NHEAD * SEQ * HDIM];
__device__ float g_Vf[BATCH * NHEAD * SEQ * HDIM];
__device__ float g_Valsf[BATCH * SEQ * DMODEL];
// half mirrors for the fp16 attention under test
__device__ __half g_Qh[BATCH * NHEAD * SEQ * HDIM];
__device__ __half g_Kh[BATCH * NHEAD * SEQ * HDIM];
__device__ __half g_Vh[BATCH * NHEAD * SEQ * HDIM];

// ---------------- helpers ----------------
__device__ __forceinline__ void cp_async16(void* smem_dst, const void* gsrc) {
    uint32_t s = (uint32_t)__cvta_generic_to_shared(smem_dst);
    asm volatile("cp.async.cg.shared.global [%0], [%1], 16;\n" :: "r"(s), "l"(gsrc));
}
__device__ __forceinline__ void cp_commit() { asm volatile("cp.async.commit_group;\n"); }
template<int N> __device__ __forceinline__ void cp_wait() {
    asm volatile("cp.async.wait_group %0;\n" :: "n"(N));
}
__device__ __forceinline__ void mma_f16(float* d, const uint32_t* a, uint32_t b0, uint32_t b1) {
    asm volatile(
        "mma.sync.aligned.m16n8k16.row.col.f32.f16.f16.f32 "
        "{%0,%1,%2,%3}, {%4,%5,%6,%7}, {%8,%9}, {%0,%1,%2,%3};\n"
        : "+f"(d[0]), "+f"(d[1]), "+f"(d[2]), "+f"(d[3])
        : "r"(a[0]), "r"(a[1]), "r"(a[2]), "r"(a[3]), "r"(b0), "r"(b1));
}
__device__ __forceinline__ uint32_t pack_f2(float lo, float hi) {
    __half2 h = __floats2half2_rn(lo, hi);
    return *reinterpret_cast<uint32_t*>(&h);
}
__device__ __forceinline__ uint32_t pack_hh(__half lo, __half hi) {
    __half2 h; h.x = lo; h.y = hi;
    return *reinterpret_cast<uint32_t*>(&h);
}

// ---------------------------------------------------------------------------
// ROUND-2 VERIFIED tf32 GEMM (verbatim): C = A[Mx1024] * B[1024xNCOLS] + bias
// MODE 0: scatter float into g_Qf/g_Kf/g_Vf.  MODE 1: A = g_Valsf, write oC.
// ---------------------------------------------------------------------------
#define GEMM_AS (128 * 36)
#define GEMM_BS (32 * 132)
#define GEMM_SMEM_FLOATS (2 * GEMM_AS + 2 * GEMM_BS + 8 * 320)

template<int NCOLS, int MODE>
__global__ __launch_bounds__(256)
void gemm_tf32(const float* __restrict__ Ain, const float* __restrict__ Bw,
               const float* __restrict__ bias, float* __restrict__ oC)
{
    extern __shared__ float sm[];
    float* As0 = sm;
    float* As1 = sm + GEMM_AS;
    float* Bs0 = sm + 2 * GEMM_AS;
    float* Bs1 = Bs0 + GEMM_BS;
    float* Cs  = Bs0 + 2 * GEMM_BS;

    const float* A = (MODE == 0) ? Ain : g_Valsf;

    const int tid  = threadIdx.x;
    const int w    = tid >> 5;
    const int lane = tid & 31;
    const int wm   = w & 3;
    const int wn   = w >> 2;
    const int m0   = blockIdx.y * 128;
    const int n0   = blockIdx.x * 128;

    wmma::fragment<wmma::accumulator, 16, 16, 8, float> acc[2][4];
#pragma unroll
    for (int i = 0; i < 2; i++)
#pragma unroll
        for (int j = 0; j < 4; j++)
            wmma::fill_fragment(acc[i][j], 0.0f);

    auto load_stage = [&](int kt, float* Ad, float* Bd) {
        const float* Asrc = A + (size_t)m0 * KDIM + kt * 32;
#pragma unroll
        for (int it = 0; it < 4; ++it) {
            int c = tid + it * 256;
            int r = c >> 3, q = c & 7;
            cp_async16(&Ad[r * 36 + q * 4], Asrc + r * KDIM + q * 4);
        }
        const float* Bsrc = Bw + (size_t)(kt * 32) * NCOLS + n0;
#pragma unroll
        for (int it = 0; it < 4; ++it) {
            int c = tid + it * 256;
            int r = c >> 5, q = c & 31;
            cp_async16(&Bd[r * 132 + q * 4], Bsrc + r * NCOLS + q * 4);
        }
    };

    load_stage(0, As0, Bs0);
    cp_commit();

    for (int kt = 0; kt < KDIM / 32; ++kt) {
        if (kt + 1 < KDIM / 32) {
            load_stage(kt + 1, (kt & 1) ? As0 : As1, (kt & 1) ? Bs0 : Bs1);
            cp_commit();
            cp_wait<1>();
        } else {
            cp_wait<0>();
        }
        __syncthreads();

        float* Ac = (kt & 1) ? As1 : As0;
        float* Bc = (kt & 1) ? Bs1 : Bs0;
#pragma unroll
        for (int kk = 0; kk < 32; kk += 8) {
            wmma::fragment<wmma::matrix_a, 16, 16, 8, wmma::precision::tf32, wmma::row_major> af[2];
            wmma::fragment<wmma::matrix_b, 16, 16, 8, wmma::precision::tf32, wmma::row_major> bf[4];
#pragma unroll
            for (int i = 0; i < 2; i++) {
                wmma::load_matrix_sync(af[i], &Ac[(wm * 32 + i * 16) * 36 + kk], 36);
#pragma unroll
                for (int e = 0; e < af[i].num_elements; e++)
                    af[i].x[e] = wmma::__float_to_tf32(af[i].x[e]);
            }
#pragma unroll
            for (int j = 0; j < 4; j++) {
                wmma::load_matrix_sync(bf[j], &Bc[kk * 132 + wn * 64 + j * 16], 132);
#pragma unroll
                for (int e = 0; e < bf[j].num_elements; e++)
                    bf[j].x[e] = wmma::__float_to_tf32(bf[j].x[e]);
            }
#pragma unroll
            for (int i = 0; i < 2; i++)
#pragma unroll
                for (int j = 0; j < 4; j++)
                    wmma::mma_sync(acc[i][j], af[i], bf[j], acc[i][j]);
        }
        __syncthreads();
    }

    // Epilogue
#pragma unroll
    for (int i = 0; i < 2; i++) {
#pragma unroll
        for (int j = 0; j < 4; j++) {
            wmma::store_matrix_sync(&Cs[w * 320], acc[i][j], 20, wmma::mem_row_major);
            __syncwarp();
            const int mbase = m0 + wm * 32 + i * 16;
            const int ebase = n0 + wn * 64 + j * 16;
            for (int t = lane; t < 256; t += 32) {
                int rr = t >> 4, cc = t & 15;
                int m = mbase + rr;
                int e = ebase + cc;
                float v = Cs[w * 320 + rr * 20 + cc] + bias[e];
                if (MODE == 0) {
                    int b = m >> 10, s = m & 1023;
                    int h = e / 192;
                    int jj = e - h * 192;
                    int dd = jj & 63;
                    float* dst = (jj < 64) ? g_Qf : (jj < 128) ? g_Kf : g_Vf;
                    dst[((b * NHEAD + h) * SEQ + s) * HDIM + dd] = v;
                } else {
                    oC[m * NCOLS + e] = v;
                }
            }
            __syncwarp();
        }
    }
}

// ---------------------------------------------------------------------------
// Trivial float -> half converts for Q/K/V (one element per thread).
// ---------------------------------------------------------------------------
__global__ void cvt_qkv(int n)
{
    int i = blockIdx.x * blockDim.x + threadIdx.x;
    if (i < n) {
        g_Qh[i] = __float2half(g_Qf[i]);
        g_Kh[i] = __float2half(g_Kf[i]);
        g_Vh[i] = __float2half(g_Vf[i]);
    }
}

// ---------------------------------------------------------------------------
// FlashAttention-2, fp16 mma m16n8k16 — COMPONENT UNDER TEST (round-5 body,
// scalar smem operand loads, register P repack). Reads half QKV, writes
// FLOAT g_Valsf so the verified tf32 GEMM2 consumes it.
// ---------------------------------------------------------------------------
#define AKVS 72                         // halves, 144B rows
#define ATTN_KV_H (64 * AKVS)
#define ATTN_SMEM (4 * ATTN_KV_H * 2)

__global__ __launch_bounds__(256)
void attn_kernel()
{
    extern __shared__ char smraw[];
    __half* Kb0 = reinterpret_cast<__half*>(smraw);
    __half* Kb1 = Kb0 + ATTN_KV_H;
    __half* Vb0 = Kb1 + ATTN_KV_H;
    __half* Vb1 = Vb0 + ATTN_KV_H;

    const int tid  = threadIdx.x;
    const int w    = tid >> 5;
    const int lane = tid & 31;
    const int g    = lane >> 2;     // groupID 0..7
    const int t4   = lane & 3;      // threadID_in_group
    const int qt = blockIdx.x, h = blockIdx.y, b = blockIdx.z;

    const __half* Qg = g_Qh + ((size_t)((b * NHEAD + h) * SEQ) + qt * 128 + w * 16) * HDIM;
    const __half* Kg = g_Kh + (size_t)((b * NHEAD + h) * SEQ) * HDIM;
    const __half* Vg = g_Vh + (size_t)((b * NHEAD + h) * SEQ) * HDIM;

    auto load_kv = [&](int kt, __half* Kd, __half* Vd) {
        const __half* Ks = Kg + (size_t)kt * 64 * HDIM;
        const __half* Vs = Vg + (size_t)kt * 64 * HDIM;
#pragma unroll
        for (int it = 0; it < 2; ++it) {
            int c = tid + it * 256;
            int r = c >> 3, q = c & 7;
            cp_async16(&Kd[r * AKVS + q * 8], Ks + r * HDIM + q * 8);
        }
#pragma unroll
        for (int it = 0; it < 2; ++it) {
            int c = tid + it * 256;
            int r = c >> 3, q = c & 7;
            cp_async16(&Vd[r * AKVS + q * 8], Vs + r * HDIM + q * 8);
        }
    };

    // Q a-frags (4 k-steps of 16), scaled by 1/sqrt(64)=0.125 (exact in fp16)
    const __half2 sc = __float2half2_rn(0.125f);
    uint32_t qa[4][4];
#pragma unroll
    for (int ks = 0; ks < 4; ++ks) {
        __half2 v0 = *reinterpret_cast<const __half2*>(Qg + g * HDIM       + ks * 16 + 2 * t4);
        __half2 v1 = *reinterpret_cast<const __half2*>(Qg + (g + 8) * HDIM + ks * 16 + 2 * t4);
        __half2 v2 = *reinterpret_cast<const __half2*>(Qg + g * HDIM       + ks * 16 + 2 * t4 + 8);
        __half2 v3 = *reinterpret_cast<const __half2*>(Qg + (g + 8) * HDIM + ks * 16 + 2 * t4 + 8);
        v0 = __hmul2(v0, sc); v1 = __hmul2(v1, sc);
        v2 = __hmul2(v2, sc); v3 = __hmul2(v3, sc);
        qa[ks][0] = *reinterpret_cast<uint32_t*>(&v0);
        qa[ks][1] = *reinterpret_cast<uint32_t*>(&v1);
        qa[ks][2] = *reinterpret_cast<uint32_t*>(&v2);
        qa[ks][3] = *reinterpret_cast<uint32_t*>(&v3);
    }

    float oacc[8][4];
#pragma unroll
    for (int j = 0; j < 8; j++)
#pragma unroll
        for (int c = 0; c < 4; c++) oacc[j][c] = 0.f;
    float m0r = -1e30f, m1r = -1e30f, l0 = 0.f, l1 = 0.f;

    load_kv(0, Kb0, Vb0);
    cp_commit();

    for (int kt = 0; kt < SEQ / 64; ++kt) {
        if (kt + 1 < SEQ / 64) {
            load_kv(kt + 1, (kt & 1) ? Kb0 : Kb1, (kt & 1) ? Vb0 : Vb1);
            cp_commit();
            cp_wait<1>();
        } else {
            cp_wait<0>();
        }
        __syncthreads();

        __half* Kc = (kt & 1) ? Kb1 : Kb0;
        __half* Vc = (kt & 1) ? Vb1 : Vb0;

        // ---- S = Q @ K^T (16 x 64 per warp) ----
        float sacc[8][4];
#pragma unroll
        for (int j = 0; j < 8; j++)
#pragma unroll
            for (int c = 0; c < 4; c++) sacc[j][c] = 0.f;

#pragma unroll
        for (int j = 0; j < 8; ++j) {
            const __half* Kr = Kc + (j * 8 + g) * AKVS;
#pragma unroll
            for (int ks = 0; ks < 4; ++ks) {
                uint32_t b0 = *reinterpret_cast<const uint32_t*>(Kr + ks * 16 + 2 * t4);
                uint32_t b1 = *reinterpret_cast<const uint32_t*>(Kr + ks * 16 + 2 * t4 + 8);
                mma_f16(sacc[j], qa[ks], b0, b1);
            }
        }

        // ---- online softmax (registers + quad shuffles) ----
        float mx0 = m0r, mx1 = m1r;
#pragma unroll
        for (int j = 0; j < 8; j++) {
            mx0 = fmaxf(mx0, fmaxf(sacc[j][0], sacc[j][1]));
            mx1 = fmaxf(mx1, fmaxf(sacc[j][2], sacc[j][3]));
        }
        mx0 = fmaxf(mx0, __shfl_xor_sync(0xffffffffu, mx0, 1));
        mx0 = fmaxf(mx0, __shfl_xor_sync(0xffffffffu, mx0, 2));
        mx1 = fmaxf(mx1, __shfl_xor_sync(0xffffffffu, mx1, 1));
        mx1 = fmaxf(mx1, __shfl_xor_sync(0xffffffffu, mx1, 2));

        float a0f = __expf(m0r - mx0);
        float a1f = __expf(m1r - mx1);
        m0r = mx0; m1r = mx1;

        float s0 = 0.f, s1 = 0.f;
#pragma unroll
        for (int j = 0; j < 8; j++) {
            float p;
            p = __expf(sacc[j][0] - mx0); sacc[j][0] = p; s0 += p;
            p = __expf(sacc[j][1] - mx0); sacc[j][1] = p; s0 += p;
            p = __expf(sacc[j][2] - mx1); sacc[j][2] = p; s1 += p;
            p = __expf(sacc[j][3] - mx1); sacc[j][3] = p; s1 += p;
        }
        s0 += __shfl_xor_sync(0xffffffffu, s0, 1);
        s0 += __shfl_xor_sync(0xffffffffu, s0, 2);
        s1 += __shfl_xor_sync(0xffffffffu, s1, 1);
        s1 += __shfl_xor_sync(0xffffffffu, s1, 2);
        l0 = l0 * a0f + s0;
        l1 = l1 * a1f + s1;

#pragma unroll
        for (int j = 0; j < 8; j++) {
            oacc[j][0] *= a0f; oacc[j][1] *= a0f;
            oacc[j][2] *= a1f; oacc[j][3] *= a1f;
        }

        // ---- repack P: C-frag -> A-frag in registers ----
        uint32_t pa[4][4];
#pragma unroll
        for (int ks = 0; ks < 4; ++ks) {
            pa[ks][0] = pack_f2(sacc[2 * ks][0],     sacc[2 * ks][1]);
            pa[ks][1] = pack_f2(sacc[2 * ks][2],     sacc[2 * ks][3]);
            pa[ks][2] = pack_f2(sacc[2 * ks + 1][0], sacc[2 * ks + 1][1]);
            pa[ks][3] = pack_f2(sacc[2 * ks + 1][2], sacc[2 * ks + 1][3]);
        }

        // ---- O += P @ V ----
#pragma unroll
        for (int jj = 0; jj < 8; ++jj) {
            const __half* Vb = Vc + jj * 8 + g;
#pragma unroll
            for (int ks = 0; ks < 4; ++ks) {
                const __half* Vr = Vb + (ks * 16 + 2 * t4) * AKVS;
                uint32_t b0 = pack_hh(Vr[0],        Vr[AKVS]);
                uint32_t b1 = pack_hh(Vr[8 * AKVS], Vr[9 * AKVS]);
                mma_f16(oacc[jj], pa[ks], b0, b1);
            }
        }
        __syncthreads();
    }

    // ---- finalize: O /= l, write FLOAT to g_Valsf [B,S,D] ----
    float inv0 = 1.f / l0, inv1 = 1.f / l1;
    const int row0 = qt * 128 + w * 16 + g;
    float* out0 = g_Valsf + (size_t)(b * SEQ + row0) * DMODEL + h * HDIM;
    float* out1 = out0 + 8 * DMODEL;
#pragma unroll
    for (int j = 0; j < 8; ++j) {
        *reinterpret_cast<float2*>(out0 + j * 8 + 2 * t4) =
            make_float2(oacc[j][0] * inv0, oacc[j][1] * inv0);
        *reinterpret_cast<float2*>(out1 + j * 8 + 2 * t4) =
            make_float2(oacc[j][2] * inv1, oacc[j][3] * inv1);
    }
}

// ---------------------------------------------------------------------------
extern "C" void kernel_launch(void* const* d_in, const int* in_sizes, int n_in,
                              void* d_out, int out_size)
{
    const float* x    = (const float*)d_in[0];
    const float* Wqkv = (const float*)d_in[1];
    const float* bqkv = (const float*)d_in[2];
    const float* Wo   = (const float*)d_in[3];
    const float* bo   = (const float*)d_in[4];
    float* out = (float*)d_out;

    const int gemm_smem = GEMM_SMEM_FLOATS * (int)sizeof(float);

    cudaFuncSetAttribute(gemm_tf32<3 * DMODEL, 0>,
                         cudaFuncAttributeMaxDynamicSharedMemorySize, gemm_smem);
    cudaFuncSetAttribute(gemm_tf32<DMODEL, 1>,
                         cudaFuncAttributeMaxDynamicSharedMemorySize, gemm_smem);
    cudaFuncSetAttribute(attn_kernel,
                         cudaFuncAttributeMaxDynamicSharedMemorySize, ATTN_SMEM);

    // 1) QKV projection (verified tf32) -> float [B,H,S,Hd]
    gemm_tf32<3 * DMODEL, 0><<<dim3(24, 64), 256, gemm_smem>>>(x, Wqkv, bqkv, nullptr);

    // 2) float -> half for attention operands
    const int nqkv = BATCH * NHEAD * SEQ * HDIM;
    cvt_qkv<<<(nqkv + 255) / 256, 256>>>(nqkv);

    // 3) fp16 attention (under test) -> float g_Valsf
    attn_kernel<<<dim3(SEQ / 128, NHEAD, BATCH), 256, ATTN_SMEM>>>();

    // 4) Output projection (verified tf32) -> d_out
    gemm_tf32<DMODEL, 1><<<dim3(8, 64), 256, gemm_smem>>>(nullptr, Wo, bo, out);
}

// round 7
// speedup vs baseline: 8.9196x; 3.2873x over previous
#include <cuda_runtime.h>
#include <cuda_fp16.h>
#include <mma.h>
#include <cstdint>

using namespace nvcuda;

#define BATCH 8
#define SEQ   1024
#define DMODEL 1024
#define NHEAD 16
#define HDIM  64
#define KDIM  1024

// Device-side scratch. NEVER pass these symbols from host code — on GB300,
// host code resolves them to the host shadow (ATS makes it silently readable)
// and you get the wrong array. Reference them in device code only.
__device__ __half g_Qh[BATCH * NHEAD * SEQ * HDIM];
__device__ __half g_Kh[BATCH * NHEAD * SEQ * HDIM];
__device__ __half g_Vh[BATCH * NHEAD * SEQ * HDIM];
__device__ __half g_Vals[BATCH * SEQ * DMODEL];
__device__ __half g_Xh[BATCH * SEQ * DMODEL];
__device__ __half g_Wqkv_h[DMODEL * 3 * DMODEL];
__device__ __half g_Wo_h[DMODEL * DMODEL];

// ---------------- helpers ----------------
__device__ __forceinline__ void cp_async16(void* smem_dst, const void* gsrc) {
    uint32_t s = (uint32_t)__cvta_generic_to_shared(smem_dst);
    asm volatile("cp.async.cg.shared.global [%0], [%1], 16;\n" :: "r"(s), "l"(gsrc));
}
__device__ __forceinline__ void cp_commit() { asm volatile("cp.async.commit_group;\n"); }
template<int N> __device__ __forceinline__ void cp_wait() {
    asm volatile("cp.async.wait_group %0;\n" :: "n"(N));
}
__device__ __forceinline__ void mma_f16(float* d, const uint32_t* a, uint32_t b0, uint32_t b1) {
    asm volatile(
        "mma.sync.aligned.m16n8k16.row.col.f32.f16.f16.f32 "
        "{%0,%1,%2,%3}, {%4,%5,%6,%7}, {%8,%9}, {%0,%1,%2,%3};\n"
        : "+f"(d[0]), "+f"(d[1]), "+f"(d[2]), "+f"(d[3])
        : "r"(a[0]), "r"(a[1]), "r"(a[2]), "r"(a[3]), "r"(b0), "r"(b1));
}
__device__ __forceinline__ uint32_t pack_f2(float lo, float hi) {
    __half2 h = __floats2half2_rn(lo, hi);
    return *reinterpret_cast<uint32_t*>(&h);
}
__device__ __forceinline__ uint32_t pack_hh(__half lo, __half hi) {
    __half2 h; h.x = lo; h.y = hi;
    return *reinterpret_cast<uint32_t*>(&h);
}

// ---------------------------------------------------------------------------
// Prep: fp32 -> fp16. Destination selected by template ID in DEVICE code.
// ---------------------------------------------------------------------------
template<int DST>
__global__ void f2h_kernel(const float* __restrict__ src, int n4) {
    __half* dst = (DST == 0) ? g_Xh : (DST == 1) ? g_Wqkv_h : g_Wo_h;
    int i = blockIdx.x * blockDim.x + threadIdx.x;
    if (i < n4) {
        float4 v = reinterpret_cast<const float4*>(src)[i];
        reinterpret_cast<__half2*>(dst)[i * 2]     = __floats2half2_rn(v.x, v.y);
        reinterpret_cast<__half2*>(dst)[i * 2 + 1] = __floats2half2_rn(v.z, v.w);
    }
}

// ---------------------------------------------------------------------------
// fp16 wmma GEMM: C[M x NCOLS] = A[M x 1024] * W[1024 x NCOLS] + bias
// BM=128 BN=128 BK=64, cp.async double-buffered, 8 warps (4x2), warp 32x64.
// A and W chosen in device code: MODE 0 = g_Xh @ g_Wqkv_h, scatter half QKV.
//                                MODE 1 = g_Vals @ g_Wo_h, fp32 row-major out.
// ---------------------------------------------------------------------------
#define BK 64
#define ASTR 72      // halves
#define BSTR 136     // halves
#define A_STAGE_H (128 * ASTR)
#define B_STAGE_H (BK * BSTR)
#define GEMM_SMEM ((2 * A_STAGE_H + 2 * B_STAGE_H) * 2 + 8 * 320 * 4)

template<int NCOLS, int MODE>
__global__ __launch_bounds__(256)
void gemm_h(const float* __restrict__ bias, float* __restrict__ oC)
{
    extern __shared__ char smraw[];
    __half* A0 = reinterpret_cast<__half*>(smraw);
    __half* A1 = A0 + A_STAGE_H;
    __half* B0 = A1 + A_STAGE_H;
    __half* B1 = B0 + B_STAGE_H;
    float*  Cs = reinterpret_cast<float*>(B1 + B_STAGE_H);

    const __half* A = (MODE == 0) ? g_Xh : g_Vals;          // device-side refs
    const __half* W = (MODE == 0) ? g_Wqkv_h : g_Wo_h;

    const int tid  = threadIdx.x;
    const int w    = tid >> 5;
    const int lane = tid & 31;
    const int wm   = w & 3;
    const int wn   = w >> 2;
    const int m0   = blockIdx.y * 128;
    const int n0   = blockIdx.x * 128;

    wmma::fragment<wmma::accumulator, 16, 16, 16, float> acc[2][4];
#pragma unroll
    for (int i = 0; i < 2; i++)
#pragma unroll
        for (int j = 0; j < 4; j++)
            wmma::fill_fragment(acc[i][j], 0.0f);

    auto load_stage = [&](int kt, __half* Ad, __half* Bd) {
        const __half* As = A + (size_t)m0 * KDIM + kt * BK;
#pragma unroll
        for (int it = 0; it < 4; ++it) {
            int c = tid + it * 256;
            int r = c >> 3, q = c & 7;
            cp_async16(&Ad[r * ASTR + q * 8], As + (size_t)r * KDIM + q * 8);
        }
        const __half* Bs = W + (size_t)(kt * BK) * NCOLS + n0;
#pragma unroll
        for (int it = 0; it < 4; ++it) {
            int c = tid + it * 256;
            int r = c >> 4, q = c & 15;
            cp_async16(&Bd[r * BSTR + q * 8], Bs + (size_t)r * NCOLS + q * 8);
        }
    };

    load_stage(0, A0, B0);
    cp_commit();

    for (int kt = 0; kt < KDIM / BK; ++kt) {
        if (kt + 1 < KDIM / BK) {
            load_stage(kt + 1, (kt & 1) ? A0 : A1, (kt & 1) ? B0 : B1);
            cp_commit();
            cp_wait<1>();
        } else {
            cp_wait<0>();
        }
        __syncthreads();

        __half* Ac = (kt & 1) ? A1 : A0;
        __half* Bc = (kt & 1) ? B1 : B0;
#pragma unroll
        for (int kk = 0; kk < BK; kk += 16) {
            wmma::fragment<wmma::matrix_a, 16, 16, 16, __half, wmma::row_major> af[2];
            wmma::fragment<wmma::matrix_b, 16, 16, 16, __half, wmma::row_major> bf[4];
#pragma unroll
            for (int i = 0; i < 2; i++)
                wmma::load_matrix_sync(af[i], &Ac[(wm * 32 + i * 16) * ASTR + kk], ASTR);
#pragma unroll
            for (int j = 0; j < 4; j++)
                wmma::load_matrix_sync(bf[j], &Bc[kk * BSTR + wn * 64 + j * 16], BSTR);
#pragma unroll
            for (int i = 0; i < 2; i++)
#pragma unroll
                for (int j = 0; j < 4; j++)
                    wmma::mma_sync(acc[i][j], af[i], bf[j], acc[i][j]);
        }
        __syncthreads();
    }

    // Epilogue: stage 16x16 per warp, add bias, write
#pragma unroll
    for (int i = 0; i < 2; i++) {
#pragma unroll
        for (int j = 0; j < 4; j++) {
            wmma::store_matrix_sync(&Cs[w * 320], acc[i][j], 20, wmma::mem_row_major);
            __syncwarp();
            const int mbase = m0 + wm * 32 + i * 16;
            const int ebase = n0 + wn * 64 + j * 16;
            for (int t = lane; t < 128; t += 32) {
                int rr = t >> 3, cc = (t & 7) * 2;
                int m = mbase + rr;
                int e = ebase + cc;
                float v0 = Cs[w * 320 + rr * 20 + cc]     + bias[e];
                float v1 = Cs[w * 320 + rr * 20 + cc + 1] + bias[e + 1];
                if (MODE == 0) {
                    int b = m >> 10, s = m & 1023;
                    int h = e / 192;
                    int jj = e - h * 192;
                    int sel = jj >> 6;
                    int dd = jj & 63;
                    __half* base = (sel == 0) ? g_Qh : (sel == 1) ? g_Kh : g_Vh;
                    *reinterpret_cast<__half2*>(
                        base + ((size_t)(b * NHEAD + h) * SEQ + s) * HDIM + dd) =
                        __floats2half2_rn(v0, v1);
                } else {
                    *reinterpret_cast<float2*>(oC + (size_t)m * NCOLS + e) =
                        make_float2(v0, v1);
                }
            }
            __syncwarp();
        }
    }
}

// ---------------------------------------------------------------------------
// FlashAttention-2, fp16 mma m16n8k16 (validated in round 6). 1 CTA per
// (b, h, 128 q-rows); 8 warps x 16 q-rows; scalar smem operand loads;
// register P repack. Writes half to g_Vals.
// ---------------------------------------------------------------------------
#define AKVS 72                         // halves, 144B rows
#define ATTN_KV_H (64 * AKVS)
#define ATTN_SMEM (4 * ATTN_KV_H * 2)

__global__ __launch_bounds__(256)
void attn_kernel()
{
    extern __shared__ char smraw[];
    __half* Kb0 = reinterpret_cast<__half*>(smraw);
    __half* Kb1 = Kb0 + ATTN_KV_H;
    __half* Vb0 = Kb1 + ATTN_KV_H;
    __half* Vb1 = Vb0 + ATTN_KV_H;

    const int tid  = threadIdx.x;
    const int w    = tid >> 5;
    const int lane = tid & 31;
    const int g    = lane >> 2;     // groupID 0..7
    const int t4   = lane & 3;      // threadID_in_group
    const int qt = blockIdx.x, h = blockIdx.y, b = blockIdx.z;

    const __half* Qg = g_Qh + ((size_t)((b * NHEAD + h) * SEQ) + qt * 128 + w * 16) * HDIM;
    const __half* Kg = g_Kh + (size_t)((b * NHEAD + h) * SEQ) * HDIM;
    const __half* Vg = g_Vh + (size_t)((b * NHEAD + h) * SEQ) * HDIM;

    auto load_kv = [&](int kt, __half* Kd, __half* Vd) {
        const __half* Ks = Kg + (size_t)kt * 64 * HDIM;
        const __half* Vs = Vg + (size_t)kt * 64 * HDIM;
#pragma unroll
        for (int it = 0; it < 2; ++it) {
            int c = tid + it * 256;
            int r = c >> 3, q = c & 7;
            cp_async16(&Kd[r * AKVS + q * 8], Ks + r * HDIM + q * 8);
        }
#pragma unroll
        for (int it = 0; it < 2; ++it) {
            int c = tid + it * 256;
            int r = c >> 3, q = c & 7;
            cp_async16(&Vd[r * AKVS + q * 8], Vs + r * HDIM + q * 8);
        }
    };

    // Q a-frags (4 k-steps of 16), scaled by 1/sqrt(64)=0.125 (exact in fp16)
    const __half2 sc = __float2half2_rn(0.125f);
    uint32_t qa[4][4];
#pragma unroll
    for (int ks = 0; ks < 4; ++ks) {
        __half2 v0 = *reinterpret_cast<const __half2*>(Qg + g * HDIM       + ks * 16 + 2 * t4);
        __half2 v1 = *reinterpret_cast<const __half2*>(Qg + (g + 8) * HDIM + ks * 16 + 2 * t4);
        __half2 v2 = *reinterpret_cast<const __half2*>(Qg + g * HDIM       + ks * 16 + 2 * t4 + 8);
        __half2 v3 = *reinterpret_cast<const __half2*>(Qg + (g + 8) * HDIM + ks * 16 + 2 * t4 + 8);
        v0 = __hmul2(v0, sc); v1 = __hmul2(v1, sc);
        v2 = __hmul2(v2, sc); v3 = __hmul2(v3, sc);
        qa[ks][0] = *reinterpret_cast<uint32_t*>(&v0);
        qa[ks][1] = *reinterpret_cast<uint32_t*>(&v1);
        qa[ks][2] = *reinterpret_cast<uint32_t*>(&v2);
        qa[ks][3] = *reinterpret_cast<uint32_t*>(&v3);
    }

    float oacc[8][4];
#pragma unroll
    for (int j = 0; j < 8; j++)
#pragma unroll
        for (int c = 0; c < 4; c++) oacc[j][c] = 0.f;
    float m0r = -1e30f, m1r = -1e30f, l0 = 0.f, l1 = 0.f;

    load_kv(0, Kb0, Vb0);
    cp_commit();

    for (int kt = 0; kt < SEQ / 64; ++kt) {
        if (kt + 1 < SEQ / 64) {
            load_kv(kt + 1, (kt & 1) ? Kb0 : Kb1, (kt & 1) ? Vb0 : Vb1);
            cp_commit();
            cp_wait<1>();
        } else {
            cp_wait<0>();
        }
        __syncthreads();

        __half* Kc = (kt & 1) ? Kb1 : Kb0;
        __half* Vc = (kt & 1) ? Vb1 : Vb0;

        // ---- S = Q @ K^T (16 x 64 per warp) ----
        float sacc[8][4];
#pragma unroll
        for (int j = 0; j < 8; j++)
#pragma unroll
            for (int c = 0; c < 4; c++) sacc[j][c] = 0.f;

#pragma unroll
        for (int j = 0; j < 8; ++j) {
            const __half* Kr = Kc + (j * 8 + g) * AKVS;
#pragma unroll
            for (int ks = 0; ks < 4; ++ks) {
                uint32_t b0 = *reinterpret_cast<const uint32_t*>(Kr + ks * 16 + 2 * t4);
                uint32_t b1 = *reinterpret_cast<const uint32_t*>(Kr + ks * 16 + 2 * t4 + 8);
                mma_f16(sacc[j], qa[ks], b0, b1);
            }
        }

        // ---- online softmax (registers + quad shuffles) ----
        float mx0 = m0r, mx1 = m1r;
#pragma unroll
        for (int j = 0; j < 8; j++) {
            mx0 = fmaxf(mx0, fmaxf(sacc[j][0], sacc[j][1]));
            mx1 = fmaxf(mx1, fmaxf(sacc[j][2], sacc[j][3]));
        }
        mx0 = fmaxf(mx0, __shfl_xor_sync(0xffffffffu, mx0, 1));
        mx0 = fmaxf(mx0, __shfl_xor_sync(0xffffffffu, mx0, 2));
        mx1 = fmaxf(mx1, __shfl_xor_sync(0xffffffffu, mx1, 1));
        mx1 = fmaxf(mx1, __shfl_xor_sync(0xffffffffu, mx1, 2));

        float a0f = __expf(m0r - mx0);
        float a1f = __expf(m1r - mx1);
        m0r = mx0; m1r = mx1;

        float s0 = 0.f, s1 = 0.f;
#pragma unroll
        for (int j = 0; j < 8; j++) {
            float p;
            p = __expf(sacc[j][0] - mx0); sacc[j][0] = p; s0 += p;
            p = __expf(sacc[j][1] - mx0); sacc[j][1] = p; s0 += p;
            p = __expf(sacc[j][2] - mx1); sacc[j][2] = p; s1 += p;
            p = __expf(sacc[j][3] - mx1); sacc[j][3] = p; s1 += p;
        }
        s0 += __shfl_xor_sync(0xffffffffu, s0, 1);
        s0 += __shfl_xor_sync(0xffffffffu, s0, 2);
        s1 += __shfl_xor_sync(0xffffffffu, s1, 1);
        s1 += __shfl_xor_sync(0xffffffffu, s1, 2);
        l0 = l0 * a0f + s0;
        l1 = l1 * a1f + s1;

#pragma unroll
        for (int j = 0; j < 8; j++) {
            oacc[j][0] *= a0f; oacc[j][1] *= a0f;
            oacc[j][2] *= a1f; oacc[j][3] *= a1f;
        }

        // ---- repack P: C-frag -> A-frag in registers ----
        uint32_t pa[4][4];
#pragma unroll
        for (int ks = 0; ks < 4; ++ks) {
            pa[ks][0] = pack_f2(sacc[2 * ks][0],     sacc[2 * ks][1]);
            pa[ks][1] = pack_f2(sacc[2 * ks][2],     sacc[2 * ks][3]);
            pa[ks][2] = pack_f2(sacc[2 * ks + 1][0], sacc[2 * ks + 1][1]);
            pa[ks][3] = pack_f2(sacc[2 * ks + 1][2], sacc[2 * ks + 1][3]);
        }

        // ---- O += P @ V ----
#pragma unroll
        for (int jj = 0; jj < 8; ++jj) {
            const __half* Vb = Vc + jj * 8 + g;
#pragma unroll
            for (int ks = 0; ks < 4; ++ks) {
                const __half* Vr = Vb + (ks * 16 + 2 * t4) * AKVS;
                uint32_t b0 = pack_hh(Vr[0],        Vr[AKVS]);
                uint32_t b1 = pack_hh(Vr[8 * AKVS], Vr[9 * AKVS]);
                mma_f16(oacc[jj], pa[ks], b0, b1);
            }
        }
        __syncthreads();
    }

    // ---- finalize: O /= l, write half to g_Vals [B,S,D] ----
    float inv0 = 1.f / l0, inv1 = 1.f / l1;
    const int row0 = qt * 128 + w * 16 + g;
    __half* out0 = g_Vals + (size_t)(b * SEQ + row0) * DMODEL + h * HDIM;
    __half* out1 = out0 + 8 * DMODEL;
#pragma unroll
    for (int j = 0; j < 8; ++j) {
        *reinterpret_cast<__half2*>(out0 + j * 8 + 2 * t4) =
            __floats2half2_rn(oacc[j][0] * inv0, oacc[j][1] * inv0);
        *reinterpret_cast<__half2*>(out1 + j * 8 + 2 * t4) =
            __floats2half2_rn(oacc[j][2] * inv1, oacc[j][3] * inv1);
    }
}

// ---------------------------------------------------------------------------
extern "C" void kernel_launch(void* const* d_in, const int* in_sizes, int n_in,
                              void* d_out, int out_size)
{
    const float* x    = (const float*)d_in[0];
    const float* Wqkv = (const float*)d_in[1];
    const float* bqkv = (const float*)d_in[2];
    const float* Wo   = (const float*)d_in[3];
    const float* bo   = (const float*)d_in[4];
    float* out = (float*)d_out;

    cudaFuncSetAttribute(gemm_h<3 * DMODEL, 0>,
                         cudaFuncAttributeMaxDynamicSharedMemorySize, GEMM_SMEM);
    cudaFuncSetAttribute(gemm_h<DMODEL, 1>,
                         cudaFuncAttributeMaxDynamicSharedMemorySize, GEMM_SMEM);
    cudaFuncSetAttribute(attn_kernel,
                         cudaFuncAttributeMaxDynamicSharedMemorySize, ATTN_SMEM);

    // 0) fp32 -> fp16 converts into device globals (selected device-side)
    f2h_kernel<0><<<(BATCH * SEQ * DMODEL / 4 + 255) / 256, 256>>>(x, BATCH * SEQ * DMODEL / 4);
    f2h_kernel<1><<<(DMODEL * 3 * DMODEL / 4 + 255) / 256, 256>>>(Wqkv, DMODEL * 3 * DMODEL / 4);
    f2h_kernel<2><<<(DMODEL * DMODEL / 4 + 255) / 256, 256>>>(Wo, DMODEL * DMODEL / 4);

    // 1) QKV projection + scatter half into [B,H,S,Hd]
    gemm_h<3 * DMODEL, 0><<<dim3(24, 64), 256, GEMM_SMEM>>>(bqkv, nullptr);

    // 2) Attention -> g_Vals (half)
    attn_kernel<<<dim3(SEQ / 128, NHEAD, BATCH), 256, ATTN_SMEM>>>();

    // 3) Output projection -> d_out (fp32)
    gemm_h<DMODEL, 1><<<dim3(8, 64), 256, GEMM_SMEM>>>(bo, out);
}